// round 8
// baseline (speedup 1.0000x reference)
#include <cuda_runtime.h>
#include <cuda_bf16.h>
#include <cstdint>

// ---------------- problem constants ----------------
#define Bsz   256
#define NBAND 7
#define HWn   16384          // 128*128
#define HID   256
#define SEL   3

#define Mtot  (Bsz*NBAND)    // 1792
#define Ktot  HWn
#define Ntot  HID

// ---------------- GEMM tiling ----------------
#define SPLITS 32
#define KC     (Ktot/SPLITS) // 512
#define BMt    64
#define BNt    256
#define BKs    32            // K per stage
#define NSTG   (KC/BKs)      // 16

// SMEM layout: padded 80B rows (64B data + 16B pad) -> conflict-free ldmatrix
#define A_VAR  5120          // 64 rows * 80B
#define A_BUF  (2*A_VAR)     // hi+lo
#define B_VAR  20480         // 256 rows * 80B
#define B_BUF  (2*B_VAR)
#define OFFB   (2*A_BUF)     // 20480
#define SMEM_TOTAL (OFFB + 2*B_BUF)   // 102400

// ---------------- scratch ----------------
__device__ float g_part[SPLITS * (size_t)Mtot * Ntot];   // 58.7 MB
__device__ float g_scores[Mtot];
__device__ int   g_top[Bsz * SEL];
__device__ int   g_flag[Bsz];
__device__ __align__(256) __nv_bfloat16 g_wt_hi[(size_t)Ntot * Ktot];  // 8 MB [n][k]
__device__ __align__(256) __nv_bfloat16 g_wt_lo[(size_t)Ntot * Ktot];  // 8 MB

// ---------------- PTX helpers (baseline sm_80 features only) ----------------
__device__ __forceinline__ uint32_t smem_u32(const void* p) {
    uint32_t a;
    asm("{ .reg .u64 t; cvta.to.shared.u64 t, %1; cvt.u32.u64 %0, t; }" : "=r"(a) : "l"(p));
    return a;
}
__device__ __forceinline__ void ldsm4(uint32_t* r, uint32_t addr) {
    asm volatile("ldmatrix.sync.aligned.m8n8.x4.shared.b16 {%0,%1,%2,%3}, [%4];"
                 : "=r"(r[0]), "=r"(r[1]), "=r"(r[2]), "=r"(r[3]) : "r"(addr));
}
__device__ __forceinline__ void mma_bf16(float* c, const uint32_t* a, const uint32_t* b) {
    asm volatile("mma.sync.aligned.m16n8k16.row.col.f32.bf16.bf16.f32 "
                 "{%0,%1,%2,%3}, {%4,%5,%6,%7}, {%8,%9}, {%0,%1,%2,%3};"
                 : "+f"(c[0]), "+f"(c[1]), "+f"(c[2]), "+f"(c[3])
                 : "r"(a[0]), "r"(a[1]), "r"(a[2]), "r"(a[3]), "r"(b[0]), "r"(b[1]));
}
__device__ __forceinline__ void cp16(uint32_t dst, const void* src) {
    uint64_t g = __cvta_generic_to_global(src);
    asm volatile("cp.async.cg.shared.global [%0], [%1], 16;" :: "r"(dst), "l"(g) : "memory");
}
#define CP_COMMIT() asm volatile("cp.async.commit_group;" ::: "memory")
#define CP_WAIT(n)  asm volatile("cp.async.wait_group %0;" :: "n"(n) : "memory")

__device__ __forceinline__ uint32_t pkbf(__nv_bfloat16 a, __nv_bfloat16 b) {
    return ((uint32_t)__bfloat16_as_ushort(b) << 16) | (uint32_t)__bfloat16_as_ushort(a);
}

// ====================================================================
// Kernel 0: transpose + split-convert w1[K][N] -> g_wt_hi/lo [N][K] bf16
// ====================================================================
__global__ void convw_kernel(const float* __restrict__ w1) {
    __shared__ float tl[32][33];
    const int kb = blockIdx.x * 32;
    const int nb = blockIdx.y * 32;
    const int tx = threadIdx.x;   // 0..31
    const int ty = threadIdx.y;   // 0..7
    #pragma unroll
    for (int i = ty; i < 32; i += 8)
        tl[i][tx] = w1[(size_t)(kb + i) * Ntot + nb + tx];
    __syncthreads();
    #pragma unroll
    for (int i = ty; i < 32; i += 8) {
        float v = tl[tx][i];
        __nv_bfloat16 h = __float2bfloat16(v);
        __nv_bfloat16 l = __float2bfloat16(v - __bfloat162float(h));
        size_t o = (size_t)(nb + i) * Ktot + kb + tx;
        g_wt_hi[o] = h;
        g_wt_lo[o] = l;
    }
}

// ====================================================================
// Kernel 1: HMMA bf16 split-accum GEMM (split-K) -> g_part
//   C[r,n] = sum_k x[r,k] * w1[k,n]
//   8 warps: 2(m) x 4(n); warp tile 32x64; mma.m16n8k16
// ====================================================================
__global__ __launch_bounds__(256, 2)
void gemm_kernel(const float* __restrict__ A) {
    extern __shared__ char smem[];
    const uint32_t sb = smem_u32(smem);
    const int tid = threadIdx.x, wid = tid >> 5, lid = tid & 31;
    const int bm    = blockIdx.x * BMt;
    const int split = blockIdx.z;
    const int kbase = split * KC;
    const int wm = wid >> 2, wn = wid & 3;

    float acc[2][8][4];
    #pragma unroll
    for (int i = 0; i < 2; i++)
        #pragma unroll
        for (int j = 0; j < 8; j++)
            #pragma unroll
            for (int q = 0; q < 4; q++) acc[i][j][q] = 0.f;

    const int ar  = tid >> 2;   // A row 0..63
    const int ac  = tid & 3;    // A col segment
    const int bn0 = tid >> 2;   // B row base
    const int bc  = tid & 3;    // B 16B chunk

    const float* Abase = A + (size_t)(bm + ar) * Ktot + kbase;

    auto loadA = [&](int s, float4* r) {
        #pragma unroll
        for (int j = 0; j < 2; j++)
            r[j] = *(const float4*)(Abase + s * BKs + (ac * 2 + j) * 4);
    };
    auto storeA = [&](int s, const float4* r) {
        const int buf = s & 1;
        char* ap = smem + buf * A_BUF + ar * 80;
        #pragma unroll
        for (int j = 0; j < 2; j++) {
            float4 v = r[j];
            __nv_bfloat16 h0 = __float2bfloat16(v.x), h1 = __float2bfloat16(v.y);
            __nv_bfloat16 h2 = __float2bfloat16(v.z), h3 = __float2bfloat16(v.w);
            __nv_bfloat16 l0 = __float2bfloat16(v.x - __bfloat162float(h0));
            __nv_bfloat16 l1 = __float2bfloat16(v.y - __bfloat162float(h1));
            __nv_bfloat16 l2 = __float2bfloat16(v.z - __bfloat162float(h2));
            __nv_bfloat16 l3 = __float2bfloat16(v.w - __bfloat162float(h3));
            const int off = (ac * 2 + j) * 8;
            *(uint2*)(ap + off)         = make_uint2(pkbf(h0, h1), pkbf(h2, h3));
            *(uint2*)(ap + A_VAR + off) = make_uint2(pkbf(l0, l1), pkbf(l2, l3));
        }
    };
    auto loadB = [&](int s) {
        const int buf = s & 1;
        const int k0 = kbase + s * BKs;
        #pragma unroll
        for (int j = 0; j < 4; j++) {
            const int n = j * 64 + bn0;
            const uint32_t dst = sb + OFFB + buf * B_BUF + n * 80 + bc * 16;
            cp16(dst,         g_wt_hi + (size_t)n * Ktot + k0 + bc * 8);
            cp16(dst + B_VAR, g_wt_lo + (size_t)n * Ktot + k0 + bc * 8);
        }
        CP_COMMIT();
    };

    {   // prologue: stages 0 and 1
        float4 r0[2];
        loadA(0, r0); storeA(0, r0); loadB(0);
        loadA(1, r0); storeA(1, r0); loadB(1);
    }

    float4 rn[2];
    #pragma unroll 1
    for (int s = 0; s < NSTG; s++) {
        if (s + 2 < NSTG) loadA(s + 2, rn);
        if (s + 2 < NSTG) { CP_WAIT(1); } else { CP_WAIT(0); }
        __syncthreads();

        const int buf = s & 1;
        const uint32_t aB = sb + buf * A_BUF;
        const uint32_t bB = sb + OFFB + buf * B_BUF;
        #pragma unroll
        for (int kk = 0; kk < 2; kk++) {
            uint32_t ah[2][4], al[2][4];
            #pragma unroll
            for (int mt = 0; mt < 2; mt++) {
                const uint32_t ad = aB +
                    (uint32_t)((wm * 32 + mt * 16 + (lid & 15)) * 80 + kk * 32 + ((lid >> 4) & 1) * 16);
                ldsm4(ah[mt], ad);
                ldsm4(al[mt], ad + A_VAR);
            }
            #pragma unroll
            for (int ng = 0; ng < 4; ng++) {
                const uint32_t bd = bB +
                    (uint32_t)((wn * 64 + ng * 16 + (lid & 7) + ((lid >> 4) & 1) * 8) * 80 +
                               kk * 32 + ((lid >> 3) & 1) * 16);
                uint32_t bh[4], bl[4];
                ldsm4(bh, bd);
                ldsm4(bl, bd + B_VAR);
                #pragma unroll
                for (int mt = 0; mt < 2; mt++) {
                    mma_bf16(acc[mt][2 * ng],     ah[mt], bh);
                    mma_bf16(acc[mt][2 * ng],     ah[mt], bl);
                    mma_bf16(acc[mt][2 * ng],     al[mt], bh);
                    mma_bf16(acc[mt][2 * ng + 1], ah[mt], bh + 2);
                    mma_bf16(acc[mt][2 * ng + 1], ah[mt], bl + 2);
                    mma_bf16(acc[mt][2 * ng + 1], al[mt], bh + 2);
                }
            }
        }
        __syncthreads();
        if (s + 2 < NSTG) { storeA(s + 2, rn); loadB(s + 2); }
    }

    // epilogue: D frag (d0,d1)=(g, 2tg..+1), (d2,d3)=(g+8, 2tg..+1)
    const int g = lid >> 2, tg = lid & 3;
    #pragma unroll
    for (int mt = 0; mt < 2; mt++) {
        const int row0 = bm + wm * 32 + mt * 16 + g;
        #pragma unroll
        for (int nt = 0; nt < 8; nt++) {
            const int col = wn * 64 + nt * 8 + tg * 2;
            float* p0 = g_part + ((size_t)split * Mtot + row0) * Ntot + col;
            float* p1 = g_part + ((size_t)split * Mtot + row0 + 8) * Ntot + col;
            *(float2*)p0 = make_float2(acc[mt][nt][0], acc[mt][nt][1]);
            *(float2*)p1 = make_float2(acc[mt][nt][2], acc[mt][nt][3]);
        }
    }
}

// ====================================================================
// Kernel 2: fused score + gap check. One block per batch element.
//   Reduces split-K partials, bias, ReLU, dot w2 -> 7 scores; then
//   flags the batch if any top-4 gap is within split-bf16 error bound.
// ====================================================================
__global__ void scoregap_kernel(const float* __restrict__ b1,
                                const float* __restrict__ w2,
                                const float* __restrict__ b2) {
    const int b = blockIdx.x;
    const int j = threadIdx.x;
    __shared__ float red[256];
    __shared__ float sc[NBAND];
    const float b1j = b1[j];
    const float w2j = w2[j];
    for (int c = 0; c < NBAND; c++) {
        const int r = b * NBAND + c;
        float h = 0.f;
        #pragma unroll
        for (int s = 0; s < SPLITS; s++)
            h += g_part[((size_t)s * Mtot + r) * Ntot + j];
        h += b1j;
        h = fmaxf(h, 0.f) * w2j;
        red[j] = h;
        __syncthreads();
        #pragma unroll
        for (int off = 128; off > 0; off >>= 1) {
            if (j < off) red[j] += red[j + off];
            __syncthreads();
        }
        if (j == 0) {
            float v = red[0] + b2[0];
            sc[c] = v;
            g_scores[r] = v;
        }
        __syncthreads();
    }
    if (j == 0) {
        float t1 = -3.4e38f, t2 = -3.4e38f, t3 = -3.4e38f, t4 = -3.4e38f;
        #pragma unroll
        for (int c = 0; c < NBAND; c++) {
            float v = sc[c];
            if (v > t1)      { t4 = t3; t3 = t2; t2 = t1; t1 = v; }
            else if (v > t2) { t4 = t3; t3 = t2; t2 = v; }
            else if (v > t3) { t4 = t3; t3 = v; }
            else if (v > t4) { t4 = v; }
        }
        float gp = fminf(t1 - t2, fminf(t2 - t3, t3 - t4));
        g_flag[b] = (gp < 1e-4f) ? 1 : 0;
    }
}

// ====================================================================
// Kernel 3: exact fp32 re-score for flagged batches
// ====================================================================
__global__ void repair_kernel(const float* __restrict__ x, const float* __restrict__ w1,
                              const float* __restrict__ b1v, const float* __restrict__ w2v,
                              const float* __restrict__ b2v) {
    const int r = blockIdx.x;
    if (g_flag[r / NBAND] == 0) return;
    const float* feat = x + (size_t)r * Ktot;
    const int j = threadIdx.x;
    __shared__ float fs[512];
    float h0 = 0.f, h1 = 0.f, h2 = 0.f, h3 = 0.f;
    for (int k0 = 0; k0 < Ktot; k0 += 512) {
        fs[j]       = feat[k0 + j];
        fs[j + 256] = feat[k0 + 256 + j];
        __syncthreads();
        #pragma unroll 4
        for (int k = 0; k < 512; k += 4) {
            h0 = fmaf(fs[k + 0], w1[(size_t)(k0 + k + 0) * Ntot + j], h0);
            h1 = fmaf(fs[k + 1], w1[(size_t)(k0 + k + 1) * Ntot + j], h1);
            h2 = fmaf(fs[k + 2], w1[(size_t)(k0 + k + 2) * Ntot + j], h2);
            h3 = fmaf(fs[k + 3], w1[(size_t)(k0 + k + 3) * Ntot + j], h3);
        }
        __syncthreads();
    }
    float h = ((h0 + h1) + (h2 + h3)) + b1v[j];
    h = fmaxf(h, 0.f) * w2v[j];
    __shared__ float red[256];
    red[j] = h;
    __syncthreads();
    #pragma unroll
    for (int off = 128; off > 0; off >>= 1) {
        if (j < off) red[j] += red[j + off];
        __syncthreads();
    }
    if (j == 0) g_scores[r] = red[0] + b2v[0];
}

// ====================================================================
// Kernel 4: stable top-3 of 7 (ties -> lower index)
// ====================================================================
__global__ void topk_kernel(float* __restrict__ out_idx, int write_idx) {
    const int b = threadIdx.x;
    float s[NBAND];
    #pragma unroll
    for (int c = 0; c < NBAND; c++) s[c] = g_scores[b * NBAND + c];
    #pragma unroll
    for (int t = 0; t < SEL; t++) {
        float best = -3.4e38f; int bi = 0;
        #pragma unroll
        for (int c = 0; c < NBAND; c++)
            if (s[c] > best) { best = s[c]; bi = c; }
        g_top[b * SEL + t] = bi;
        s[bi] = -3.4e38f;
        if (write_idx) out_idx[b * SEL + t] = (float)bi;
    }
}

// ====================================================================
// Kernel 5: gather selected bands (512 threads, 8 float4 per thread)
// ====================================================================
__global__ void gather_kernel(const float* __restrict__ x, float* __restrict__ out) {
    const int bs  = blockIdx.x;
    const int b   = bs / SEL;
    const int idx = g_top[bs];
    const float4* src = (const float4*)(x + ((size_t)b * NBAND + idx) * HWn);
    float4* dst = (float4*)(out + (size_t)bs * HWn);
    #pragma unroll 8
    for (int i = threadIdx.x; i < HWn / 4; i += 512) dst[i] = src[i];
}

// ====================================================================
extern "C" void kernel_launch(void* const* d_in, const int* in_sizes, int n_in,
                              void* d_out, int out_size) {
    const float* x  = (const float*)d_in[0];
    const float* w1 = (const float*)d_in[3];
    const float* b1 = (const float*)d_in[4];
    const float* w2 = (const float*)d_in[5];
    const float* b2 = (const float*)d_in[6];
    float* out = (float*)d_out;

    const long long sel_elems = (long long)Bsz * SEL * HWn;
    const int write_idx = ((long long)out_size >= sel_elems + Bsz * SEL) ? 1 : 0;

    cudaFuncSetAttribute(gemm_kernel, cudaFuncAttributeMaxDynamicSharedMemorySize, SMEM_TOTAL);

    dim3 gW(Ktot / 32, Ntot / 32);
    convw_kernel<<<gW, dim3(32, 8)>>>(w1);

    dim3 gG(Mtot / BMt, 1, SPLITS);          // 28 x 32 = 896 CTAs (finer wave granularity)
    gemm_kernel<<<gG, 256, SMEM_TOTAL>>>(x);

    scoregap_kernel<<<Bsz, 256>>>(b1, w2, b2);
    repair_kernel<<<Mtot, 256>>>(x, w1, b1, w2, b2);
    topk_kernel<<<1, Bsz>>>(out + sel_elems, write_idx);
    gather_kernel<<<Bsz * SEL, 512>>>(x, out);
}

// round 9
// speedup vs baseline: 1.0157x; 1.0157x over previous
#include <cuda_runtime.h>
#include <cuda_bf16.h>
#include <cstdint>

// ---------------- problem constants ----------------
#define Bsz   256
#define NBAND 7
#define HWn   16384          // 128*128
#define HID   256
#define SEL   3

#define Mtot  (Bsz*NBAND)    // 1792
#define Ktot  HWn
#define Ntot  HID

// ---------------- GEMM tiling ----------------
#define SPLITS 10            // 28 x 10 = 280 CTAs = one full wave at occ 2
#define BMt    64
#define BNt    256
#define BKs    32            // K per stage
#define TOTSTG (Ktot/BKs)    // 512 stages total, split unevenly (52,52,51x8)

// SMEM layout: padded 80B rows (64B data + 16B pad) -> conflict-free ldmatrix
#define A_VAR  5120          // 64 rows * 80B
#define A_BUF  (2*A_VAR)     // hi+lo
#define B_VAR  20480         // 256 rows * 80B
#define B_BUF  (2*B_VAR)
#define OFFB   (2*A_BUF)     // 20480
#define SMEM_TOTAL (OFFB + 2*B_BUF)   // 102400

// ---------------- scratch ----------------
__device__ float g_part[SPLITS * (size_t)Mtot * Ntot];   // 18.3 MB
__device__ float g_scores[Mtot];
__device__ int   g_top[Bsz * SEL];
__device__ int   g_flag[Bsz];
__device__ __align__(256) __nv_bfloat16 g_wt_hi[(size_t)Ntot * Ktot];  // 8 MB [n][k]
__device__ __align__(256) __nv_bfloat16 g_wt_lo[(size_t)Ntot * Ktot];  // 8 MB

// ---------------- PTX helpers (baseline sm_80 features only) ----------------
__device__ __forceinline__ uint32_t smem_u32(const void* p) {
    uint32_t a;
    asm("{ .reg .u64 t; cvta.to.shared.u64 t, %1; cvt.u32.u64 %0, t; }" : "=r"(a) : "l"(p));
    return a;
}
__device__ __forceinline__ void ldsm4(uint32_t* r, uint32_t addr) {
    asm volatile("ldmatrix.sync.aligned.m8n8.x4.shared.b16 {%0,%1,%2,%3}, [%4];"
                 : "=r"(r[0]), "=r"(r[1]), "=r"(r[2]), "=r"(r[3]) : "r"(addr));
}
__device__ __forceinline__ void mma_bf16(float* c, const uint32_t* a, const uint32_t* b) {
    asm volatile("mma.sync.aligned.m16n8k16.row.col.f32.bf16.bf16.f32 "
                 "{%0,%1,%2,%3}, {%4,%5,%6,%7}, {%8,%9}, {%0,%1,%2,%3};"
                 : "+f"(c[0]), "+f"(c[1]), "+f"(c[2]), "+f"(c[3])
                 : "r"(a[0]), "r"(a[1]), "r"(a[2]), "r"(a[3]), "r"(b[0]), "r"(b[1]));
}
__device__ __forceinline__ void cp16(uint32_t dst, const void* src) {
    uint64_t g = __cvta_generic_to_global(src);
    asm volatile("cp.async.cg.shared.global [%0], [%1], 16;" :: "r"(dst), "l"(g) : "memory");
}
#define CP_COMMIT() asm volatile("cp.async.commit_group;" ::: "memory")
#define CP_WAIT(n)  asm volatile("cp.async.wait_group %0;" :: "n"(n) : "memory")

__device__ __forceinline__ uint32_t pkbf(__nv_bfloat16 a, __nv_bfloat16 b) {
    return ((uint32_t)__bfloat16_as_ushort(b) << 16) | (uint32_t)__bfloat16_as_ushort(a);
}

// ====================================================================
// Kernel 0: transpose + split-convert w1[K][N] -> g_wt_hi/lo [N][K] bf16
// ====================================================================
__global__ void convw_kernel(const float* __restrict__ w1) {
    __shared__ float tl[32][33];
    const int kb = blockIdx.x * 32;
    const int nb = blockIdx.y * 32;
    const int tx = threadIdx.x;   // 0..31
    const int ty = threadIdx.y;   // 0..7
    #pragma unroll
    for (int i = ty; i < 32; i += 8)
        tl[i][tx] = w1[(size_t)(kb + i) * Ntot + nb + tx];
    __syncthreads();
    #pragma unroll
    for (int i = ty; i < 32; i += 8) {
        float v = tl[tx][i];
        __nv_bfloat16 h = __float2bfloat16(v);
        __nv_bfloat16 l = __float2bfloat16(v - __bfloat162float(h));
        size_t o = (size_t)(nb + i) * Ktot + kb + tx;
        g_wt_hi[o] = h;
        g_wt_lo[o] = l;
    }
}

// ====================================================================
// Kernel 1: HMMA bf16 split-accum GEMM (uneven split-K) -> g_part
//   C[r,n] = sum_k x[r,k] * w1[k,n]
//   8 warps: 2(m) x 4(n); warp tile 32x64; mma.m16n8k16
// ====================================================================
__global__ __launch_bounds__(256, 2)
void gemm_kernel(const float* __restrict__ A) {
    extern __shared__ char smem[];
    const uint32_t sb = smem_u32(smem);
    const int tid = threadIdx.x, wid = tid >> 5, lid = tid & 31;
    const int bm    = blockIdx.x * BMt;
    const int split = blockIdx.z;

    // uneven split: first (TOTSTG % SPLITS) splits take one extra stage
    const int base = TOTSTG / SPLITS;            // 51
    const int rem  = TOTSTG % SPLITS;            // 2
    const int sst  = split * base + min(split, rem);
    const int NS   = base + (split < rem ? 1 : 0);
    const int kbase = sst * BKs;

    const int wm = wid >> 2, wn = wid & 3;

    float acc[2][8][4];
    #pragma unroll
    for (int i = 0; i < 2; i++)
        #pragma unroll
        for (int j = 0; j < 8; j++)
            #pragma unroll
            for (int q = 0; q < 4; q++) acc[i][j][q] = 0.f;

    const int ar  = tid >> 2;   // A row 0..63
    const int ac  = tid & 3;    // A col segment
    const int bn0 = tid >> 2;   // B row base
    const int bc  = tid & 3;    // B 16B chunk

    const float* Abase = A + (size_t)(bm + ar) * Ktot + kbase;

    auto loadA = [&](int s, float4* r) {
        #pragma unroll
        for (int j = 0; j < 2; j++)
            r[j] = *(const float4*)(Abase + s * BKs + (ac * 2 + j) * 4);
    };
    auto storeA = [&](int s, const float4* r) {
        const int buf = s & 1;
        char* ap = smem + buf * A_BUF + ar * 80;
        #pragma unroll
        for (int j = 0; j < 2; j++) {
            float4 v = r[j];
            __nv_bfloat16 h0 = __float2bfloat16(v.x), h1 = __float2bfloat16(v.y);
            __nv_bfloat16 h2 = __float2bfloat16(v.z), h3 = __float2bfloat16(v.w);
            __nv_bfloat16 l0 = __float2bfloat16(v.x - __bfloat162float(h0));
            __nv_bfloat16 l1 = __float2bfloat16(v.y - __bfloat162float(h1));
            __nv_bfloat16 l2 = __float2bfloat16(v.z - __bfloat162float(h2));
            __nv_bfloat16 l3 = __float2bfloat16(v.w - __bfloat162float(h3));
            const int off = (ac * 2 + j) * 8;
            *(uint2*)(ap + off)         = make_uint2(pkbf(h0, h1), pkbf(h2, h3));
            *(uint2*)(ap + A_VAR + off) = make_uint2(pkbf(l0, l1), pkbf(l2, l3));
        }
    };
    auto loadB = [&](int s) {
        const int buf = s & 1;
        const int k0 = kbase + s * BKs;
        #pragma unroll
        for (int j = 0; j < 4; j++) {
            const int n = j * 64 + bn0;
            const uint32_t dst = sb + OFFB + buf * B_BUF + n * 80 + bc * 16;
            cp16(dst,         g_wt_hi + (size_t)n * Ktot + k0 + bc * 8);
            cp16(dst + B_VAR, g_wt_lo + (size_t)n * Ktot + k0 + bc * 8);
        }
        CP_COMMIT();
    };

    {   // prologue: stages 0 and 1 (NS >= 51 always)
        float4 r0[2];
        loadA(0, r0); storeA(0, r0); loadB(0);
        loadA(1, r0); storeA(1, r0); loadB(1);
    }

    float4 rn[2];
    #pragma unroll 1
    for (int s = 0; s < NS; s++) {
        if (s + 2 < NS) loadA(s + 2, rn);
        if (s + 2 < NS) { CP_WAIT(1); } else { CP_WAIT(0); }
        __syncthreads();

        const int buf = s & 1;
        const uint32_t aB = sb + buf * A_BUF;
        const uint32_t bB = sb + OFFB + buf * B_BUF;
        #pragma unroll
        for (int kk = 0; kk < 2; kk++) {
            uint32_t ah[2][4], al[2][4];
            #pragma unroll
            for (int mt = 0; mt < 2; mt++) {
                const uint32_t ad = aB +
                    (uint32_t)((wm * 32 + mt * 16 + (lid & 15)) * 80 + kk * 32 + ((lid >> 4) & 1) * 16);
                ldsm4(ah[mt], ad);
                ldsm4(al[mt], ad + A_VAR);
            }
            #pragma unroll
            for (int ng = 0; ng < 4; ng++) {
                const uint32_t bd = bB +
                    (uint32_t)((wn * 64 + ng * 16 + (lid & 7) + ((lid >> 4) & 1) * 8) * 80 +
                               kk * 32 + ((lid >> 3) & 1) * 16);
                uint32_t bh[4], bl[4];
                ldsm4(bh, bd);
                ldsm4(bl, bd + B_VAR);
                #pragma unroll
                for (int mt = 0; mt < 2; mt++) {
                    mma_bf16(acc[mt][2 * ng],     ah[mt], bh);
                    mma_bf16(acc[mt][2 * ng],     ah[mt], bl);
                    mma_bf16(acc[mt][2 * ng],     al[mt], bh);
                    mma_bf16(acc[mt][2 * ng + 1], ah[mt], bh + 2);
                    mma_bf16(acc[mt][2 * ng + 1], ah[mt], bl + 2);
                    mma_bf16(acc[mt][2 * ng + 1], al[mt], bh + 2);
                }
            }
        }
        __syncthreads();
        if (s + 2 < NS) { storeA(s + 2, rn); loadB(s + 2); }
    }

    // epilogue: D frag (d0,d1)=(g, 2tg..+1), (d2,d3)=(g+8, 2tg..+1)
    const int g = lid >> 2, tg = lid & 3;
    #pragma unroll
    for (int mt = 0; mt < 2; mt++) {
        const int row0 = bm + wm * 32 + mt * 16 + g;
        #pragma unroll
        for (int nt = 0; nt < 8; nt++) {
            const int col = wn * 64 + nt * 8 + tg * 2;
            float* p0 = g_part + ((size_t)split * Mtot + row0) * Ntot + col;
            float* p1 = g_part + ((size_t)split * Mtot + row0 + 8) * Ntot + col;
            *(float2*)p0 = make_float2(acc[mt][nt][0], acc[mt][nt][1]);
            *(float2*)p1 = make_float2(acc[mt][nt][2], acc[mt][nt][3]);
        }
    }
}

// ====================================================================
// Kernel 2: fused score + gap check. One block per batch element.
// ====================================================================
__global__ void scoregap_kernel(const float* __restrict__ b1,
                                const float* __restrict__ w2,
                                const float* __restrict__ b2) {
    const int b = blockIdx.x;
    const int j = threadIdx.x;
    __shared__ float red[256];
    __shared__ float sc[NBAND];
    const float b1j = b1[j];
    const float w2j = w2[j];
    for (int c = 0; c < NBAND; c++) {
        const int r = b * NBAND + c;
        float h = 0.f;
        #pragma unroll
        for (int s = 0; s < SPLITS; s++)
            h += g_part[((size_t)s * Mtot + r) * Ntot + j];
        h += b1j;
        h = fmaxf(h, 0.f) * w2j;
        red[j] = h;
        __syncthreads();
        #pragma unroll
        for (int off = 128; off > 0; off >>= 1) {
            if (j < off) red[j] += red[j + off];
            __syncthreads();
        }
        if (j == 0) {
            float v = red[0] + b2[0];
            sc[c] = v;
            g_scores[r] = v;
        }
        __syncthreads();
    }
    if (j == 0) {
        float t1 = -3.4e38f, t2 = -3.4e38f, t3 = -3.4e38f, t4 = -3.4e38f;
        #pragma unroll
        for (int c = 0; c < NBAND; c++) {
            float v = sc[c];
            if (v > t1)      { t4 = t3; t3 = t2; t2 = t1; t1 = v; }
            else if (v > t2) { t4 = t3; t3 = t2; t2 = v; }
            else if (v > t3) { t4 = t3; t3 = v; }
            else if (v > t4) { t4 = v; }
        }
        float gp = fminf(t1 - t2, fminf(t2 - t3, t3 - t4));
        g_flag[b] = (gp < 1e-4f) ? 1 : 0;
    }
}

// ====================================================================
// Kernel 3: exact fp32 re-score for flagged batches
// ====================================================================
__global__ void repair_kernel(const float* __restrict__ x, const float* __restrict__ w1,
                              const float* __restrict__ b1v, const float* __restrict__ w2v,
                              const float* __restrict__ b2v) {
    const int r = blockIdx.x;
    if (g_flag[r / NBAND] == 0) return;
    const float* feat = x + (size_t)r * Ktot;
    const int j = threadIdx.x;
    __shared__ float fs[512];
    float h0 = 0.f, h1 = 0.f, h2 = 0.f, h3 = 0.f;
    for (int k0 = 0; k0 < Ktot; k0 += 512) {
        fs[j]       = feat[k0 + j];
        fs[j + 256] = feat[k0 + 256 + j];
        __syncthreads();
        #pragma unroll 4
        for (int k = 0; k < 512; k += 4) {
            h0 = fmaf(fs[k + 0], w1[(size_t)(k0 + k + 0) * Ntot + j], h0);
            h1 = fmaf(fs[k + 1], w1[(size_t)(k0 + k + 1) * Ntot + j], h1);
            h2 = fmaf(fs[k + 2], w1[(size_t)(k0 + k + 2) * Ntot + j], h2);
            h3 = fmaf(fs[k + 3], w1[(size_t)(k0 + k + 3) * Ntot + j], h3);
        }
        __syncthreads();
    }
    float h = ((h0 + h1) + (h2 + h3)) + b1v[j];
    h = fmaxf(h, 0.f) * w2v[j];
    __shared__ float red[256];
    red[j] = h;
    __syncthreads();
    #pragma unroll
    for (int off = 128; off > 0; off >>= 1) {
        if (j < off) red[j] += red[j + off];
        __syncthreads();
    }
    if (j == 0) g_scores[r] = red[0] + b2v[0];
}

// ====================================================================
// Kernel 4: stable top-3 of 7 (ties -> lower index)
// ====================================================================
__global__ void topk_kernel(float* __restrict__ out_idx, int write_idx) {
    const int b = threadIdx.x;
    float s[NBAND];
    #pragma unroll
    for (int c = 0; c < NBAND; c++) s[c] = g_scores[b * NBAND + c];
    #pragma unroll
    for (int t = 0; t < SEL; t++) {
        float best = -3.4e38f; int bi = 0;
        #pragma unroll
        for (int c = 0; c < NBAND; c++)
            if (s[c] > best) { best = s[c]; bi = c; }
        g_top[b * SEL + t] = bi;
        s[bi] = -3.4e38f;
        if (write_idx) out_idx[b * SEL + t] = (float)bi;
    }
}

// ====================================================================
// Kernel 5: gather selected bands (512 threads, 8 float4 per thread)
// ====================================================================
__global__ void gather_kernel(const float* __restrict__ x, float* __restrict__ out) {
    const int bs  = blockIdx.x;
    const int b   = bs / SEL;
    const int idx = g_top[bs];
    const float4* src = (const float4*)(x + ((size_t)b * NBAND + idx) * HWn);
    float4* dst = (float4*)(out + (size_t)bs * HWn);
    #pragma unroll 8
    for (int i = threadIdx.x; i < HWn / 4; i += 512) dst[i] = src[i];
}

// ====================================================================
extern "C" void kernel_launch(void* const* d_in, const int* in_sizes, int n_in,
                              void* d_out, int out_size) {
    const float* x  = (const float*)d_in[0];
    const float* w1 = (const float*)d_in[3];
    const float* b1 = (const float*)d_in[4];
    const float* w2 = (const float*)d_in[5];
    const float* b2 = (const float*)d_in[6];
    float* out = (float*)d_out;

    const long long sel_elems = (long long)Bsz * SEL * HWn;
    const int write_idx = ((long long)out_size >= sel_elems + Bsz * SEL) ? 1 : 0;

    cudaFuncSetAttribute(gemm_kernel, cudaFuncAttributeMaxDynamicSharedMemorySize, SMEM_TOTAL);

    dim3 gW(Ktot / 32, Ntot / 32);
    convw_kernel<<<gW, dim3(32, 8)>>>(w1);

    dim3 gG(Mtot / BMt, 1, SPLITS);          // 28 x 10 = 280 CTAs (one wave at occ 2)
    gemm_kernel<<<gG, 256, SMEM_TOTAL>>>(x);

    scoregap_kernel<<<Bsz, 256>>>(b1, w2, b2);
    repair_kernel<<<Mtot, 256>>>(x, w1, b1, w2, b2);
    topk_kernel<<<1, Bsz>>>(out + sel_elems, write_idx);
    gather_kernel<<<Bsz * SEL, 512>>>(x, out);
}